// round 1
// baseline (speedup 1.0000x reference)
#include <cuda_runtime.h>
#include <math.h>

#define DIMX 512
#define CBD  14
#define CBS  16384
#define NTHR 256
#define NBLK 296

// Persistent device scratch (allocation-free rule: __device__ globals).
__device__ float g_avgp[CBS];
__device__ float g_scal[2];   // [0] = per-sample entropy sum, [1] = commit sum

__global__ void lfq_zero() {
    int i = blockIdx.x * blockDim.x + threadIdx.x;
    if (i < CBS) g_avgp[i] = 0.0f;
    if (i < 2)   g_scal[i] = 0.0f;
}

__global__ __launch_bounds__(NTHR) void lfq_main(
    const float* __restrict__ x,
    const float* __restrict__ w_in,
    const float* __restrict__ b_in,
    const float* __restrict__ w_out,
    const float* __restrict__ b_out,
    float* __restrict__ out,
    float* __restrict__ idxf,
    int ntok)
{
    const int tid  = threadIdx.x;
    const int lane = tid & 31;
    const int wid  = tid >> 5;

    // ---- register-resident weights (loaded once per block) ----
    // w_in: thread owns columns 2*tid, 2*tid+1 for all 14 dims
    float wi0[CBD], wi1[CBD];
#pragma unroll
    for (int d = 0; d < CBD; d++) {
        float2 w = *(const float2*)(w_in + d * DIMX + 2 * tid);
        wi0[d] = w.x; wi1[d] = w.y;
    }
    // w_out: thread owns output rows e0=2*tid, e1=2*tid+1 (each 14 floats,
    // 28 contiguous floats = 7 float4, 16B-aligned since 112*tid % 16 == 0)
    float wo0[CBD], wo1[CBD];
    {
        float4 tmp[7];
        const float4* wp = (const float4*)(w_out + (size_t)(2 * tid) * CBD);
#pragma unroll
        for (int i = 0; i < 7; i++) tmp[i] = wp[i];
        const float* tf = (const float*)tmp;
#pragma unroll
        for (int d = 0; d < CBD; d++) { wo0[d] = tf[d]; wo1[d] = tf[CBD + d]; }
    }
    const float bo0 = b_out[2 * tid];
    const float bo1 = b_out[2 * tid + 1];

    __shared__ float sh_part[8][CBD];
    __shared__ float sh_h[CBD];
    __shared__ float sh_q[CBD];

    for (int t = blockIdx.x; t < ntok; t += gridDim.x) {
        // ---- h = x[t] @ w_in^T + b_in ----
        float2 xv = *(const float2*)(x + (size_t)t * DIMX + 2 * tid);
        float part[CBD];
#pragma unroll
        for (int d = 0; d < CBD; d++)
            part[d] = fmaf(xv.x, wi0[d], xv.y * wi1[d]);
#pragma unroll
        for (int off = 16; off; off >>= 1) {
#pragma unroll
            for (int d = 0; d < CBD; d++)
                part[d] += __shfl_xor_sync(0xffffffffu, part[d], off);
        }
        if (lane == 0) {
#pragma unroll
            for (int d = 0; d < CBD; d++) sh_part[wid][d] = part[d];
        }
        __syncthreads();
        if (tid < CBD) {
            float hv = __ldg(b_in + tid);
#pragma unroll
            for (int w = 0; w < 8; w++) hv += sh_part[w][tid];
            sh_h[tid] = hv;
            sh_q[tid] = (hv > 0.0f) ? 1.0f : -1.0f;
        }
        __syncthreads();

        // ---- out[t] = quant @ w_out^T + b_out (quant = sign(h)) ----
        float a0 = bo0, a1 = bo1;
#pragma unroll
        for (int d = 0; d < CBD; d++) {
            float s = sh_q[d];
            a0 = fmaf(s, wo0[d], a0);
            a1 = fmaf(s, wo1[d], a1);
        }
        *(float2*)(out + (size_t)t * DIMX + 2 * tid) = make_float2(a0, a1);

        // ---- scalar per-token stats: index, commit, entropy, avg_prob ----
        // softmax over 16384 sign codes factorizes: logit_j = 200 * sum_d (+-h_d).
        // log p_j = 200*s_j - logZ, logZ = sum_d (200|h_d| + log1p(e^{-400|h_d|})).
        // Only codes flipping dims with 400*sum|h| < 40 have p > 4e-18; enumerate those.
        if (tid == 0) {
            float E = 0.0f, commit = 0.0f, lpmax = 0.0f;
            int idx = 0, k = 0;
            float wts[CBD];
            int   msk[CBD];
#pragma unroll
            for (int d = 0; d < CBD; d++) {
                float hv = sh_h[d];
                float a  = fabsf(hv);
                if (hv > 0.0f) idx |= (1 << (13 - d));
                float dm = a - 1.0f;          // (h - sign(h))^2 = (|h|-1)^2
                commit += dm * dm;
                float e4 = 400.0f * a;
                if (e4 < 40.0f) {
                    lpmax -= log1pf(__expf(-e4));
                    wts[k] = e4;
                    msk[k] = 1 << (13 - d);
                    k++;
                }
            }
            const float LCLIP = -11.512925465f;  // log(1e-5)
            const int M = 1 << k;
            for (int m = 0; m < M; m++) {
                float lp = lpmax;
                int flip = 0;
                for (int i = 0; i < k; i++) {
                    if ((m >> i) & 1) { lp -= wts[i]; flip |= msk[i]; }
                }
                float p = __expf(lp);
                E -= p * fmaxf(lp, LCLIP);
                atomicAdd(&g_avgp[idx ^ flip], p);
            }
            atomicAdd(&g_scal[0], E);
            atomicAdd(&g_scal[1], commit);
            idxf[t] = (float)idx;
        }
        __syncthreads();  // protect sh_* for next token
    }
}

__global__ __launch_bounds__(512) void lfq_final(float* __restrict__ aux, int ntok)
{
    __shared__ float red[16];
    const int tid = threadIdx.x;
    const float inv_n = 1.0f / (float)ntok;
    float s = 0.0f;
    for (int j = tid; j < CBS; j += 512) {
        float a = g_avgp[j] * inv_n;
        // -a * log(clip(a, 1e-5)); a==0 contributes exactly 0
        s -= a * logf(fmaxf(a, 1e-5f));
    }
#pragma unroll
    for (int o = 16; o; o >>= 1) s += __shfl_xor_sync(0xffffffffu, s, o);
    if ((tid & 31) == 0) red[tid >> 5] = s;
    __syncthreads();
    if (tid < 32) {
        float v = (tid < 16) ? red[tid] : 0.0f;
#pragma unroll
        for (int o = 16; o; o >>= 1) v += __shfl_xor_sync(0xffffffffu, v, o);
        if (tid == 0) {
            float cbent = v;                                    // codebook entropy
            float ps    = g_scal[0] * inv_n;                    // per-sample entropy
            float cm    = g_scal[1] * (inv_n / (float)CBD);     // commit mse
            // aux = ENT_W*(ps - GAMMA*cbent) + COMMIT_W*commit
            aux[0] = 0.1f * (ps - cbent) + 0.25f * cm;
        }
    }
}

extern "C" void kernel_launch(void* const* d_in, const int* in_sizes, int n_in,
                              void* d_out, int out_size)
{
    const float* x     = (const float*)d_in[0];
    const float* w_in  = (const float*)d_in[1];
    const float* b_in  = (const float*)d_in[2];
    const float* w_out = (const float*)d_in[3];
    const float* b_out = (const float*)d_in[4];

    const int ntok = in_sizes[0] / DIMX;   // 2*2048 = 4096

    float* out  = (float*)d_out;                     // ntok*512 floats
    float* idxf = out + (size_t)ntok * DIMX;         // ntok floats (indices)
    float* aux  = idxf + ntok;                       // 1 float (aux_loss)

    lfq_zero<<<(CBS + 255) / 256, 256>>>();
    int grid = NBLK < ntok ? NBLK : ntok;
    lfq_main<<<grid, NTHR>>>(x, w_in, b_in, w_out, b_out, out, idxf, ntok);
    lfq_final<<<1, 512>>>(aux, ntok);
}

// round 2
// speedup vs baseline: 1.5070x; 1.5070x over previous
#include <cuda_runtime.h>
#include <math.h>

#define DIMX 512
#define CBD  14
#define CBS  16384
#define NTHR 256
#define TPB  32           // tokens per block-group
#define MAXBLK 128

typedef unsigned long long ull;

// Persistent device scratch (zero-initialized at load; lfq_final re-zeros after use)
__device__ float g_avgp[CBS];
__device__ float g_scal[2];   // [0] entropy sum, [1] commit sum

// ---- packed f32x2 helpers (FFMA2: only reachable via PTX fma.rn.f32x2) ----
__device__ __forceinline__ ull ffma2(ull a, ull b, ull c) {
    ull d; asm("fma.rn.f32x2 %0, %1, %2, %3;" : "=l"(d) : "l"(a), "l"(b), "l"(c)); return d;
}
__device__ __forceinline__ ull fadd2(ull a, ull b) {
    ull d; asm("add.rn.f32x2 %0, %1, %2;" : "=l"(d) : "l"(a), "l"(b)); return d;
}
__device__ __forceinline__ ull pack2(float lo, float hi) {
    ull r; asm("mov.b64 %0, {%1, %2};" : "=l"(r) : "f"(lo), "f"(hi)); return r;
}
__device__ __forceinline__ void unpack2(ull v, float& lo, float& hi) {
    asm("mov.b64 {%0, %1}, %2;" : "=f"(lo), "=f"(hi) : "l"(v));
}

// shared-memory layout (bytes)
#define O_X 0                 // 32 rows x 129 ull2 (512 floats + 16B pad) = 66048
#define O_W 66048             // w_in staged: 14*128 ull2 = 28672
#define O_P 94720             // partials: 8*14*32 ull = 28672
#define O_H 123392            // h: 14*32 floats = 1792
#define O_Q 125184            // q(+-1): 14*32 floats = 1792
#define SMEM_TOTAL 126976

__global__ void __launch_bounds__(NTHR, 1) lfq_main(
    const float* __restrict__ x,
    const float* __restrict__ w_in,
    const float* __restrict__ b_in,
    const float* __restrict__ w_out,
    const float* __restrict__ b_out,
    float* __restrict__ out,
    float* __restrict__ idxf,
    int ntok)
{
    extern __shared__ unsigned char smem[];
    ulonglong2* sx  = (ulonglong2*)(smem + O_X);
    ulonglong2* swi = (ulonglong2*)(smem + O_W);
    ull*        sp  = (ull*)       (smem + O_P);
    float*      shh = (float*)     (smem + O_H);
    float*      shq = (float*)     (smem + O_Q);

    const int tid  = threadIdx.x;
    const int lane = tid & 31;
    const int wid  = tid >> 5;

    // stage w_in [14][512] into shared once (coalesced, 28KB)
    {
        const ulonglong2* wsrc = (const ulonglong2*)w_in;
#pragma unroll
        for (int i = 0; i < 7; i++) swi[i * 256 + tid] = wsrc[i * 256 + tid];
    }

    for (int base = blockIdx.x * TPB; base < ntok; base += gridDim.x * TPB) {
        __syncthreads();   // protect shared reuse across groups (and order w_in staging)

        // ---- stage 32 token rows of x into padded shared (coalesced) ----
#pragma unroll
        for (int i = 0; i < 16; i++) {
            int idx = i * 256 + tid;
            int t = idx >> 7, c = idx & 127;
            ulonglong2 v;
            if (base + t < ntok) v = *(const ulonglong2*)(x + (size_t)(base + t) * DIMX + c * 4);
            else { v.x = 0ull; v.y = 0ull; }
            sx[t * 129 + c] = v;
        }
        __syncthreads();

        // ---- phase 1: h = x @ w_in^T  (lane = token, warp = 64-col chunk) ----
        ull acc[CBD];
#pragma unroll
        for (int d = 0; d < CBD; d++) acc[d] = 0ull;
        {
            const ulonglong2* xs = sx + lane * 129 + wid * 16;   // this token, this chunk
            const ulonglong2* ws = swi + wid * 16;               // broadcast reads
#pragma unroll 4
            for (int j = 0; j < 16; j++) {
                ulonglong2 xv = xs[j];
#pragma unroll
                for (int d = 0; d < CBD; d++) {
                    ulonglong2 wv = ws[d * 128 + j];
                    acc[d] = ffma2(xv.x, wv.x, ffma2(xv.y, wv.y, acc[d]));
                }
            }
        }
#pragma unroll
        for (int d = 0; d < CBD; d++) sp[wid * 448 + d * 32 + lane] = acc[d];
        __syncthreads();

        // ---- cross-warp reduce (packed), add b_in, compute sign ----
#pragma unroll
        for (int r = 0; r < 2; r++) {
            int p = tid + r * 256;
            if (p < 448) {
                ull s = 0ull;
#pragma unroll
                for (int w = 0; w < 8; w++) s = fadd2(s, sp[w * 448 + p]);
                float lo, hi; unpack2(s, lo, hi);
                float h = lo + hi + __ldg(b_in + (p >> 5));
                shh[p] = h;
                shq[p] = (h > 0.0f) ? 1.0f : -1.0f;
            }
        }
        __syncthreads();

        // ---- phase 2: out = q @ w_out^T  (thread = output column e, token-paired f32x2) ----
#pragma unroll 1
        for (int pass = 0; pass < 2; pass++) {
            int e = tid + pass * 256;
            float wo[CBD];
#pragma unroll
            for (int d = 0; d < CBD; d++) wo[d] = __ldg(w_out + e * CBD + d);
            float bo = __ldg(b_out + e);
            ull a2[16];
            ull binit = pack2(bo, bo);
#pragma unroll
            for (int tp = 0; tp < 16; tp++) a2[tp] = binit;
#pragma unroll
            for (int d = 0; d < CBD; d++) {
                ull wsp = pack2(wo[d], wo[d]);
                const ull* qrow = (const ull*)(shq + d * 32);    // broadcast reads
#pragma unroll
                for (int tp = 0; tp < 16; tp++)
                    a2[tp] = ffma2(qrow[tp], wsp, a2[tp]);
            }
#pragma unroll
            for (int tp = 0; tp < 16; tp++) {
                float lo, hi; unpack2(a2[tp], lo, hi);
                int t0 = base + 2 * tp;
                if (t0 < ntok)     out[(size_t)t0 * DIMX + e]       = lo;  // coalesced over e
                if (t0 + 1 < ntok) out[(size_t)(t0 + 1) * DIMX + e] = hi;
            }
        }

        // ---- entropy / index / commit: warp 0, lane = token (parallel, no shuffles of h) ----
        if (wid == 0) {
            int t = base + lane;
            float E = 0.0f, commit = 0.0f, lpmax = 0.0f;
            int idx = 0, k = 0;
            float wts[CBD]; int msk[CBD];
            if (t < ntok) {
#pragma unroll
                for (int d = 0; d < CBD; d++) {
                    float hv = shh[d * 32 + lane];
                    float a = fabsf(hv);
                    if (hv > 0.0f) idx |= 1 << (13 - d);
                    float dm = a - 1.0f;
                    commit += dm * dm;
                    float e4 = 400.0f * a;
                    if (e4 < 40.0f) { lpmax -= log1pf(__expf(-e4)); wts[k] = e4; msk[k] = 1 << (13 - d); k++; }
                }
                const float LCLIP = -11.512925465f;   // log(1e-5)
                const int M = 1 << k;
                for (int m = 0; m < M; m++) {
                    float lp = lpmax; int flip = 0;
                    for (int i = 0; i < k; i++)
                        if ((m >> i) & 1) { lp -= wts[i]; flip |= msk[i]; }
                    float p = __expf(lp);
                    E -= p * fmaxf(lp, LCLIP);
                    atomicAdd(&g_avgp[idx ^ flip], p);
                }
                idxf[t] = (float)idx;
            }
#pragma unroll
            for (int o = 16; o; o >>= 1) {
                E      += __shfl_xor_sync(0xffffffffu, E, o);
                commit += __shfl_xor_sync(0xffffffffu, commit, o);
            }
            if (lane == 0) { atomicAdd(&g_scal[0], E); atomicAdd(&g_scal[1], commit); }
        }
    }
}

__global__ void __launch_bounds__(1024) lfq_final(float* __restrict__ aux, int ntok)
{
    __shared__ float red[32];
    const int tid = threadIdx.x;
    const float inv_n = 1.0f / (float)ntok;
    float s = 0.0f;
    for (int j = tid; j < CBS; j += 1024) {
        float v = g_avgp[j];
        g_avgp[j] = 0.0f;                      // reset for next graph replay
        float a = v * inv_n;
        s -= a * logf(fmaxf(a, 1e-5f));        // a==0 contributes exactly 0
    }
#pragma unroll
    for (int o = 16; o; o >>= 1) s += __shfl_xor_sync(0xffffffffu, s, o);
    if ((tid & 31) == 0) red[tid >> 5] = s;
    __syncthreads();
    if (tid < 32) {
        float v = red[tid];
#pragma unroll
        for (int o = 16; o; o >>= 1) v += __shfl_xor_sync(0xffffffffu, v, o);
        if (tid == 0) {
            float cbent = v;
            float ps = g_scal[0] * inv_n;
            float cm = g_scal[1] * (inv_n / (float)CBD);
            g_scal[0] = 0.0f; g_scal[1] = 0.0f;  // reset for next replay
            aux[0] = 0.1f * (ps - cbent) + 0.25f * cm;
        }
    }
}

extern "C" void kernel_launch(void* const* d_in, const int* in_sizes, int n_in,
                              void* d_out, int out_size)
{
    const float* x     = (const float*)d_in[0];
    const float* w_in  = (const float*)d_in[1];
    const float* b_in  = (const float*)d_in[2];
    const float* w_out = (const float*)d_in[3];
    const float* b_out = (const float*)d_in[4];

    const int ntok = in_sizes[0] / DIMX;   // 4096

    float* out  = (float*)d_out;
    float* idxf = out + (size_t)ntok * DIMX;
    float* aux  = idxf + ntok;

    cudaFuncSetAttribute(lfq_main, cudaFuncAttributeMaxDynamicSharedMemorySize, SMEM_TOTAL);

    int nblk = (ntok + TPB - 1) / TPB;
    if (nblk > MAXBLK) nblk = MAXBLK;
    lfq_main<<<nblk, NTHR, SMEM_TOTAL>>>(x, w_in, b_in, w_out, b_out, out, idxf, ntok);
    lfq_final<<<1, 1024>>>(aux, ntok);
}

// round 3
// speedup vs baseline: 1.7662x; 1.1719x over previous
#include <cuda_runtime.h>
#include <math.h>

#define DIMX 512
#define CBD  14
#define CBS  16384
#define NTHR 256
#define TPB  32           // tokens per block-group
#define MAXBLK 128
#define FINBLK 64

typedef unsigned long long ull;

// Persistent device scratch (zero-initialized at load; lfq_final re-zeros after use)
__device__ float g_avgp[CBS];
__device__ float g_scal[2];          // [0] entropy sum, [1] commit sum
__device__ float g_ent;              // codebook-entropy partial accumulator
__device__ unsigned int g_ctr;       // final-kernel block arrival counter

// ---- packed f32x2 helpers (FFMA2: only reachable via PTX fma.rn.f32x2) ----
__device__ __forceinline__ ull ffma2(ull a, ull b, ull c) {
    ull d; asm("fma.rn.f32x2 %0, %1, %2, %3;" : "=l"(d) : "l"(a), "l"(b), "l"(c)); return d;
}
__device__ __forceinline__ ull fadd2(ull a, ull b) {
    ull d; asm("add.rn.f32x2 %0, %1, %2;" : "=l"(d) : "l"(a), "l"(b)); return d;
}
__device__ __forceinline__ ull pack2(float lo, float hi) {
    ull r; asm("mov.b64 %0, {%1, %2};" : "=l"(r) : "f"(lo), "f"(hi)); return r;
}
__device__ __forceinline__ void unpack2(ull v, float& lo, float& hi) {
    asm("mov.b64 {%0, %1}, %2;" : "=f"(lo), "=f"(hi) : "l"(v));
}

// shared-memory layout (bytes)
#define O_X 0                 // 32 rows x 129 ull2 (512 floats + 16B pad) = 66048
#define O_W 66048             // w_in staged: 14*128 ull2 = 28672
#define O_P 94720             // partials: 8*14*32 ull = 28672
#define O_H 123392            // h: 14*32 floats = 1792
#define O_Q 125184            // q(+-1): 14*32 floats = 1792
#define SMEM_TOTAL 126976

__global__ void __launch_bounds__(NTHR, 1) lfq_main(
    const float* __restrict__ x,
    const float* __restrict__ w_in,
    const float* __restrict__ b_in,
    const float* __restrict__ w_out,
    const float* __restrict__ b_out,
    float* __restrict__ out,
    float* __restrict__ idxf,
    int ntok)
{
    extern __shared__ unsigned char smem[];
    ulonglong2* sx  = (ulonglong2*)(smem + O_X);
    ulonglong2* swi = (ulonglong2*)(smem + O_W);
    ull*        sp  = (ull*)       (smem + O_P);
    float*      shh = (float*)     (smem + O_H);
    float*      shq = (float*)     (smem + O_Q);

    const int tid  = threadIdx.x;
    const int lane = tid & 31;
    const int wid  = tid >> 5;

    // stage w_in [14][512] into shared once (coalesced, 28KB)
    {
        const ulonglong2* wsrc = (const ulonglong2*)w_in;
#pragma unroll
        for (int i = 0; i < 7; i++) swi[i * 256 + tid] = wsrc[i * 256 + tid];
    }

    for (int base = blockIdx.x * TPB; base < ntok; base += gridDim.x * TPB) {
        __syncthreads();   // protect shared reuse across groups (and order w_in staging)

        // ---- stage 32 token rows of x into padded shared (coalesced) ----
#pragma unroll
        for (int i = 0; i < 16; i++) {
            int idx = i * 256 + tid;
            int t = idx >> 7, c = idx & 127;
            ulonglong2 v;
            if (base + t < ntok) v = *(const ulonglong2*)(x + (size_t)(base + t) * DIMX + c * 4);
            else { v.x = 0ull; v.y = 0ull; }
            sx[t * 129 + c] = v;
        }
        __syncthreads();

        // ---- phase 1: h = x @ w_in^T  (lane = token, warp = 64-col chunk) ----
        ull acc[CBD];
#pragma unroll
        for (int d = 0; d < CBD; d++) acc[d] = 0ull;
        {
            const ulonglong2* xs = sx + lane * 129 + wid * 16;   // this token, this chunk
            const ulonglong2* ws = swi + wid * 16;               // broadcast reads
#pragma unroll 4
            for (int j = 0; j < 16; j++) {
                ulonglong2 xv = xs[j];
#pragma unroll
                for (int d = 0; d < CBD; d++) {
                    ulonglong2 wv = ws[d * 128 + j];
                    acc[d] = ffma2(xv.x, wv.x, ffma2(xv.y, wv.y, acc[d]));
                }
            }
        }
#pragma unroll
        for (int d = 0; d < CBD; d++) sp[wid * 448 + d * 32 + lane] = acc[d];
        __syncthreads();

        // ---- cross-warp reduce (tree, packed), add b_in, compute sign ----
#pragma unroll
        for (int r = 0; r < 2; r++) {
            int p = tid + r * 256;
            if (p < 448) {
                ull s0 = fadd2(sp[0 * 448 + p], sp[1 * 448 + p]);
                ull s1 = fadd2(sp[2 * 448 + p], sp[3 * 448 + p]);
                ull s2 = fadd2(sp[4 * 448 + p], sp[5 * 448 + p]);
                ull s3 = fadd2(sp[6 * 448 + p], sp[7 * 448 + p]);
                ull s  = fadd2(fadd2(s0, s1), fadd2(s2, s3));
                float lo, hi; unpack2(s, lo, hi);
                float h = lo + hi + __ldg(b_in + (p >> 5));
                shh[p] = h;
                shq[p] = (h > 0.0f) ? 1.0f : -1.0f;
            }
        }
        __syncthreads();

        // ---- phase 2: out = q @ w_out^T  (thread = output column e, token-paired f32x2) ----
#pragma unroll 1
        for (int pass = 0; pass < 2; pass++) {
            int e = tid + pass * 256;
            float wo[CBD];
#pragma unroll
            for (int d = 0; d < CBD; d++) wo[d] = __ldg(w_out + e * CBD + d);
            float bo = __ldg(b_out + e);
            ull a2[16];
            ull binit = pack2(bo, bo);
#pragma unroll
            for (int tp = 0; tp < 16; tp++) a2[tp] = binit;
#pragma unroll
            for (int d = 0; d < CBD; d++) {
                ull wsp = pack2(wo[d], wo[d]);
                const ull* qrow = (const ull*)(shq + d * 32);    // broadcast reads
#pragma unroll
                for (int tp = 0; tp < 16; tp++)
                    a2[tp] = ffma2(qrow[tp], wsp, a2[tp]);
            }
#pragma unroll
            for (int tp = 0; tp < 16; tp++) {
                float lo, hi; unpack2(a2[tp], lo, hi);
                int t0 = base + 2 * tp;
                if (t0 < ntok)     out[(size_t)t0 * DIMX + e]       = lo;  // coalesced over e
                if (t0 + 1 < ntok) out[(size_t)(t0 + 1) * DIMX + e] = hi;
            }
        }

        // ---- entropy / index / commit: warp 0, lane = token (parallel) ----
        if (wid == 0) {
            int t = base + lane;
            float E = 0.0f, commit = 0.0f, lpmax = 0.0f;
            int idx = 0, k = 0;
            float wts[CBD]; int msk[CBD];
            if (t < ntok) {
#pragma unroll
                for (int d = 0; d < CBD; d++) {
                    float hv = shh[d * 32 + lane];
                    float a = fabsf(hv);
                    if (hv > 0.0f) idx |= 1 << (13 - d);
                    float dm = a - 1.0f;
                    commit += dm * dm;
                    float e4 = 400.0f * a;
                    if (e4 < 40.0f) { lpmax -= log1pf(__expf(-e4)); wts[k] = e4; msk[k] = 1 << (13 - d); k++; }
                }
                const float LCLIP = -11.512925465f;   // log(1e-5)
                const int M = 1 << k;
                for (int m = 0; m < M; m++) {
                    float lp = lpmax; int flip = 0;
                    for (int i = 0; i < k; i++)
                        if ((m >> i) & 1) { lp -= wts[i]; flip |= msk[i]; }
                    float p = __expf(lp);
                    E -= p * fmaxf(lp, LCLIP);
                    atomicAdd(&g_avgp[idx ^ flip], p);
                }
                idxf[t] = (float)idx;
            }
#pragma unroll
            for (int o = 16; o; o >>= 1) {
                E      += __shfl_xor_sync(0xffffffffu, E, o);
                commit += __shfl_xor_sync(0xffffffffu, commit, o);
            }
            if (lane == 0) { atomicAdd(&g_scal[0], E); atomicAdd(&g_scal[1], commit); }
        }
    }
}

// grid=FINBLK x 256: one bin per thread; last-arriving block finishes scalar math.
__global__ void __launch_bounds__(256) lfq_final(float* __restrict__ aux, int ntok)
{
    __shared__ float red[8];
    __shared__ bool amlast;
    const int tid = threadIdx.x;
    const int j = blockIdx.x * 256 + tid;       // FINBLK*256 == CBS
    const float inv_n = 1.0f / (float)ntok;

    float v = g_avgp[j];
    g_avgp[j] = 0.0f;                           // reset for next graph replay
    float a = v * inv_n;
    float s = -a * logf(fmaxf(a, 1e-5f));       // a==0 contributes exactly 0

#pragma unroll
    for (int o = 16; o; o >>= 1) s += __shfl_xor_sync(0xffffffffu, s, o);
    if ((tid & 31) == 0) red[tid >> 5] = s;
    __syncthreads();
    if (tid == 0) {
        float bs = red[0];
#pragma unroll
        for (int w = 1; w < 8; w++) bs += red[w];
        atomicAdd(&g_ent, bs);
        __threadfence();
        unsigned int old = atomicAdd(&g_ctr, 1u);
        amlast = (old == (unsigned)(gridDim.x - 1));
    }
    __syncthreads();
    if (amlast && tid == 0) {
        float cbent = g_ent;
        float ps = g_scal[0] * inv_n;
        float cm = g_scal[1] * (inv_n / (float)CBD);
        aux[0] = 0.1f * (ps - cbent) + 0.25f * cm;
        // reset persistent state for next replay
        g_ent = 0.0f; g_ctr = 0u; g_scal[0] = 0.0f; g_scal[1] = 0.0f;
    }
}

extern "C" void kernel_launch(void* const* d_in, const int* in_sizes, int n_in,
                              void* d_out, int out_size)
{
    const float* x     = (const float*)d_in[0];
    const float* w_in  = (const float*)d_in[1];
    const float* b_in  = (const float*)d_in[2];
    const float* w_out = (const float*)d_in[3];
    const float* b_out = (const float*)d_in[4];

    const int ntok = in_sizes[0] / DIMX;   // 4096

    float* out  = (float*)d_out;
    float* idxf = out + (size_t)ntok * DIMX;
    float* aux  = idxf + ntok;

    cudaFuncSetAttribute(lfq_main, cudaFuncAttributeMaxDynamicSharedMemorySize, SMEM_TOTAL);

    int nblk = (ntok + TPB - 1) / TPB;
    if (nblk > MAXBLK) nblk = MAXBLK;
    lfq_main<<<nblk, NTHR, SMEM_TOTAL>>>(x, w_in, b_in, w_out, b_out, out, idxf, ntok);
    lfq_final<<<FINBLK, 256>>>(aux, ntok);
}